// round 1
// baseline (speedup 1.0000x reference)
#include <cuda_runtime.h>
#include <cstdint>
#include <math.h>

// Problem dims
#define NB 512
#define NZ 64
#define NH 256
#define NG 768   // 3*H
#define NT 64
#define NP 10000
#define MTOT (NB * NT)   // 32768

// ---------------- scratch (device globals; no allocations allowed) ----------
__device__ float g_h0[NB * NH];
__device__ float g_g0[NG];                  // layer0 input gates (same for all b,t)
__device__ float g_WT0[NH * NG];            // W_hh0 transposed: [k][g]
__device__ float g_WT1[NH * NG];
__device__ float g_st0[2][NB * NH];         // layer0 hidden ping-pong
__device__ float g_st1[2][NB * NH];         // layer1 hidden ping-pong
__device__ float g_y0[MTOT * NH];           // layer0 outputs (B,T,H)
__device__ float g_gx1[(size_t)MTOT * NG];  // layer1 input gates (B,T,3H)
__device__ float g_y1[MTOT * NH];           // layer1 outputs (pre-LN)
__device__ float g_act[MTOT * NH];          // post LN+ELU activations

// ---------------- helpers ----------------------------------------------------
__device__ __forceinline__ float f2tf32(float f) {
    uint32_t u;
    asm("cvt.rna.tf32.f32 %0, %1;" : "=r"(u) : "f"(f));
    return __uint_as_float(u);
}

__device__ __forceinline__ void mma_tf32(float* c, const uint32_t* a, const uint32_t* b) {
    asm volatile(
        "mma.sync.aligned.m16n8k8.row.col.f32.tf32.tf32.f32 "
        "{%0,%1,%2,%3},{%4,%5,%6,%7},{%8,%9},{%0,%1,%2,%3};"
        : "+f"(c[0]), "+f"(c[1]), "+f"(c[2]), "+f"(c[3])
        : "r"(a[0]), "r"(a[1]), "r"(a[2]), "r"(a[3]), "r"(b[0]), "r"(b[1]));
}

// ---------------- prep 1: h0 = ELU(z @ W_init^T + b_init); g0 ---------------
__global__ void prep1_kernel(const float* __restrict__ z,
                             const float* __restrict__ Wi,
                             const float* __restrict__ bi,
                             const float* __restrict__ emb,
                             const float* __restrict__ Wih0,
                             const float* __restrict__ bih0) {
    int blk = blockIdx.x;
    int tid = threadIdx.x;   // 256
    if (blk < NB) {
        __shared__ float zs[NZ];
        if (tid < NZ) zs[tid] = z[blk * NZ + tid];
        __syncthreads();
        float acc = bi[tid];
        #pragma unroll 8
        for (int k = 0; k < NZ; k++) acc = fmaf(zs[k], Wi[tid * NZ + k], acc);
        float h = acc > 0.f ? acc : (expf(acc) - 1.f);
        g_h0[blk * NH + tid] = h;
        g_st0[0][blk * NH + tid] = h;
        g_st1[0][blk * NH + tid] = h;
    } else {
        __shared__ float es[NH];
        es[tid] = emb[tid];
        __syncthreads();
        int g = (blk - NB) * NH + tid;   // 3 blocks -> 768 outputs
        float acc = bih0[g];
        #pragma unroll 8
        for (int k = 0; k < NH; k++) acc = fmaf(es[k], Wih0[g * NH + k], acc);
        g_g0[g] = acc;
    }
}

// ---------------- prep 2: transpose W_hh -> [k][g] ---------------------------
__global__ void prep2_kernel(const float* __restrict__ Whh0,
                             const float* __restrict__ Whh1) {
    int i = blockIdx.x * blockDim.x + threadIdx.x;   // [0, 2*H*G)
    const int n = NH * NG;
    if (i < n) {
        int k = i / NG, g = i % NG;
        g_WT0[i] = Whh0[g * NH + k];
    } else {
        int j = i - n;
        int k = j / NG, g = j % NG;
        g_WT1[j] = Whh1[g * NH + k];
    }
}

// ---------------- GRU step: gh = h @ Whh^T + bhh; gate; update ---------------
// grid (64, 2), block 128. Each block: 8 batch rows x 128 hidden units.
__global__ void gru_step_kernel(int layer, int t, const float* __restrict__ bhh) {
    const float* WT = layer ? g_WT1 : g_WT0;
    const float* h_in = layer ? g_st1[t & 1] : g_st0[t & 1];
    float* h_out = layer ? g_st1[(t + 1) & 1] : g_st0[(t + 1) & 1];
    float* y = (layer ? g_y1 : g_y0) + t * NH;
    const float* gx = layer ? (g_gx1 + (size_t)t * NG) : g_g0;
    const int gxs = layer ? NT * NG : 0;

    const int BB = 8;
    int b0 = blockIdx.x * BB;
    int j = blockIdx.y * 128 + threadIdx.x;

    __shared__ float sh[BB * NH];
    const float* hp = h_in + b0 * NH;
    #pragma unroll
    for (int i = 0; i < (BB * NH) / 128; i++)
        sh[i * 128 + threadIdx.x] = hp[i * 128 + threadIdx.x];
    __syncthreads();

    float ar[BB], au[BB], an[BB];
    #pragma unroll
    for (int bb = 0; bb < BB; bb++) { ar[bb] = 0.f; au[bb] = 0.f; an[bb] = 0.f; }

    const float* w0 = WT + j;
    #pragma unroll 4
    for (int k = 0; k < NH; k++) {
        float wr = w0[k * NG];
        float wz = w0[k * NG + NH];
        float wn = w0[k * NG + 2 * NH];
        #pragma unroll
        for (int bb = 0; bb < BB; bb++) {
            float hk = sh[bb * NH + k];
            ar[bb] = fmaf(wr, hk, ar[bb]);
            au[bb] = fmaf(wz, hk, au[bb]);
            an[bb] = fmaf(wn, hk, an[bb]);
        }
    }

    float br = bhh[j], bz = bhh[NH + j], bn = bhh[2 * NH + j];
    #pragma unroll
    for (int bb = 0; bb < BB; bb++) {
        int b = b0 + bb;
        const float* gxb = gx + (size_t)b * gxs;
        float xr = gxb[j], xz = gxb[NH + j], xn = gxb[2 * NH + j];
        float r = 1.f / (1.f + __expf(-(xr + ar[bb] + br)));
        float u = 1.f / (1.f + __expf(-(xz + au[bb] + bz)));
        float n = tanhf(xn + r * (an[bb] + bn));
        float hprev = sh[bb * NH + j];
        float hnew = (1.f - u) * n + u * hprev;
        h_out[(size_t)b * NH + j] = hnew;
        y[(size_t)b * (NT * NH) + j] = hnew;
    }
}

// ---------------- LayerNorm + ELU (one row per block, 256 threads) -----------
__global__ void ln_elu_kernel(const float* __restrict__ gam,
                              const float* __restrict__ bet) {
    int row = blockIdx.x;
    int tid = threadIdx.x;
    float v = g_y1[(size_t)row * NH + tid];

    __shared__ float red[8];
    float s = v;
    #pragma unroll
    for (int o = 16; o; o >>= 1) s += __shfl_xor_sync(0xffffffffu, s, o);
    if ((tid & 31) == 0) red[tid >> 5] = s;
    __syncthreads();
    float tot = red[0] + red[1] + red[2] + red[3] + red[4] + red[5] + red[6] + red[7];
    float mu = tot * (1.f / NH);
    __syncthreads();

    float d = v - mu;
    s = d * d;
    #pragma unroll
    for (int o = 16; o; o >>= 1) s += __shfl_xor_sync(0xffffffffu, s, o);
    if ((tid & 31) == 0) red[tid >> 5] = s;
    __syncthreads();
    tot = red[0] + red[1] + red[2] + red[3] + red[4] + red[5] + red[6] + red[7];
    float var = tot * (1.f / NH);

    float yv = d * rsqrtf(var + 1e-5f) * gam[tid] + bet[tid];
    yv = yv > 0.f ? yv : (__expf(yv) - 1.f);
    g_act[(size_t)row * NH + tid] = yv;
}

// ---------------- tf32 GEMM: C = A(M x 256) * Bm(N x 256)^T + bias -----------
// which==0: A = g_y0, C = g_gx1 (gx1 GEMM). which==1: A = g_act, C = Cout.
// Block tile 128x128, Ktile 32, 256 threads (2x4 warps, warp tile 64x32).
__global__ __launch_bounds__(256) void gemm_tf32_kernel(
    int which, const float* __restrict__ Bm, const float* __restrict__ bias,
    float* __restrict__ Cout, int N) {
    const int K = NH;  // 256
    const float* A = which ? g_act : g_y0;
    float* C = which ? Cout : g_gx1;

    __shared__ float As[128 * 36];
    __shared__ float Bs[128 * 36];

    int tid = threadIdx.x;
    int lane = tid & 31;
    int warp = tid >> 5;
    int wm = warp & 1;
    int wn = warp >> 1;
    int m0 = blockIdx.y * 128;
    int n0 = blockIdx.x * 128;

    float acc[4][4][4];
    #pragma unroll
    for (int a = 0; a < 4; a++)
        #pragma unroll
        for (int b = 0; b < 4; b++)
            #pragma unroll
            for (int c = 0; c < 4; c++) acc[a][b][c] = 0.f;

    for (int kt = 0; kt < K; kt += 32) {
        #pragma unroll
        for (int i = 0; i < 4; i++) {
            int f = i * 256 + tid;        // 1024 float4 tiles
            int r = f >> 3;
            int c = (f & 7) << 2;
            float4 va = *(const float4*)(A + (size_t)(m0 + r) * K + kt + c);
            float* da = &As[r * 36 + c];
            da[0] = f2tf32(va.x); da[1] = f2tf32(va.y);
            da[2] = f2tf32(va.z); da[3] = f2tf32(va.w);

            int n = n0 + r;
            float4 vb = make_float4(0.f, 0.f, 0.f, 0.f);
            if (n < N) vb = *(const float4*)(Bm + (size_t)n * K + kt + c);
            float* db = &Bs[r * 36 + c];
            db[0] = f2tf32(vb.x); db[1] = f2tf32(vb.y);
            db[2] = f2tf32(vb.z); db[3] = f2tf32(vb.w);
        }
        __syncthreads();

        #pragma unroll
        for (int kk = 0; kk < 4; kk++) {
            int kb = kk * 8;
            uint32_t af[4][4];
            uint32_t bf[4][2];
            int ra = wm * 64 + (lane >> 2);
            int ca = kb + (lane & 3);
            #pragma unroll
            for (int mf = 0; mf < 4; mf++) {
                const float* p = &As[(ra + mf * 16) * 36 + ca];
                af[mf][0] = __float_as_uint(p[0]);
                af[mf][1] = __float_as_uint(p[8 * 36]);
                af[mf][2] = __float_as_uint(p[4]);
                af[mf][3] = __float_as_uint(p[8 * 36 + 4]);
            }
            int rb = wn * 32 + (lane >> 2);
            #pragma unroll
            for (int nf = 0; nf < 4; nf++) {
                const float* p = &Bs[(rb + nf * 8) * 36 + ca];
                bf[nf][0] = __float_as_uint(p[0]);
                bf[nf][1] = __float_as_uint(p[4]);
            }
            #pragma unroll
            for (int mf = 0; mf < 4; mf++)
                #pragma unroll
                for (int nf = 0; nf < 4; nf++)
                    mma_tf32(acc[mf][nf], af[mf], bf[nf]);
        }
        __syncthreads();
    }

    // epilogue: add bias, store
    #pragma unroll
    for (int mf = 0; mf < 4; mf++) {
        int row = m0 + wm * 64 + mf * 16 + (lane >> 2);
        #pragma unroll
        for (int nf = 0; nf < 4; nf++) {
            int col = n0 + wn * 32 + nf * 8 + (lane & 3) * 2;
            if (col < N) {
                float2 bv = *(const float2*)(bias + col);
                float2 o0 = make_float2(acc[mf][nf][0] + bv.x, acc[mf][nf][1] + bv.y);
                float2 o1 = make_float2(acc[mf][nf][2] + bv.x, acc[mf][nf][3] + bv.y);
                *(float2*)(C + (size_t)row * N + col) = o0;
                *(float2*)(C + (size_t)(row + 8) * N + col) = o1;
            }
        }
    }
}

// ---------------- launch -----------------------------------------------------
extern "C" void kernel_launch(void* const* d_in, const int* in_sizes, int n_in,
                              void* d_out, int out_size) {
    const float* z      = (const float*)d_in[0];
    const float* W_init = (const float*)d_in[1];
    const float* b_init = (const float*)d_in[2];
    const float* emb    = (const float*)d_in[3];
    const float* W_ih0  = (const float*)d_in[4];
    const float* W_hh0  = (const float*)d_in[5];
    // b_ih0 = d_in[6] folded into g_g0
    const float* b_hh0  = (const float*)d_in[7];
    const float* W_ih1  = (const float*)d_in[8];
    const float* W_hh1  = (const float*)d_in[9];
    const float* b_ih1  = (const float*)d_in[10];
    const float* b_hh1  = (const float*)d_in[11];
    const float* ln_g   = (const float*)d_in[12];
    const float* ln_b   = (const float*)d_in[13];
    const float* W_out  = (const float*)d_in[14];
    const float* b_out  = (const float*)d_in[15];
    const float* b_ih0  = (const float*)d_in[6];
    float* out = (float*)d_out;

    // init: h0, g0, weight transposes
    prep1_kernel<<<NB + 3, 256>>>(z, W_init, b_init, emb, W_ih0, b_ih0);
    prep2_kernel<<<(2 * NH * NG) / 256, 256>>>(W_hh0, W_hh1);

    // GRU layer 0 (input gates are the constant g0)
    for (int t = 0; t < NT; t++)
        gru_step_kernel<<<dim3(NB / 8, 2), 128>>>(0, t, b_hh0);

    // layer-1 input gates for all timesteps at once: gx1 = Y0 @ W_ih1^T + b_ih1
    gemm_tf32_kernel<<<dim3(NG / 128, MTOT / 128), 256>>>(0, W_ih1, b_ih1, nullptr, NG);

    // GRU layer 1
    for (int t = 0; t < NT; t++)
        gru_step_kernel<<<dim3(NB / 8, 2), 128>>>(1, t, b_hh1);

    // LayerNorm + ELU
    ln_elu_kernel<<<MTOT, 256>>>(ln_g, ln_b);

    // logits = act @ W_out^T + b_out
    gemm_tf32_kernel<<<dim3((NP + 127) / 128, MTOT / 128), 256>>>(1, W_out, b_out, out, NP);
}

// round 2
// speedup vs baseline: 2.7395x; 2.7395x over previous
#include <cuda_runtime.h>
#include <cstdint>
#include <math.h>

// Problem dims
#define NB 512
#define NZ 64
#define NH 256
#define NG 768   // 3*H
#define NT 64
#define NP 10000
#define MTOT (NB * NT)   // 32768

#define NBLK 128         // persistent GRU grid (16 batch x 8 hidden blocks)
#define AS_STRIDE 268    // 32-row h tile, conflict-free padding
#define WS_STRIDE 260    // 96-row weight tile, conflict-free padding
#define GRU_SMEM ((32 * AS_STRIDE + 96 * WS_STRIDE) * 4)

// ---------------- scratch (device globals; no allocations allowed) ----------
__device__ float g_h0[NB * NH];
__device__ float g_g0[NG];                  // layer0 input gates (same for all b,t)
__device__ float g_st0[2][NB * NH];         // layer0 hidden ping-pong
__device__ float g_st1[2][NB * NH];         // layer1 hidden ping-pong
__device__ float g_y0[MTOT * NH];           // layer0 outputs (B,T,H)
__device__ float g_gx1[(size_t)MTOT * NG];  // layer1 input gates (B,T,3H)
__device__ float g_y1[MTOT * NH];           // layer1 outputs (pre-LN)
__device__ float g_act[MTOT * NH];          // post LN+ELU activations
__device__ unsigned g_cnt[2][NT];           // grid-barrier counters (reset each replay)

// ---------------- helpers ----------------------------------------------------
__device__ __forceinline__ float f2tf32(float f) {
    uint32_t u;
    asm("cvt.rna.tf32.f32 %0, %1;" : "=r"(u) : "f"(f));
    return __uint_as_float(u);
}

__device__ __forceinline__ void mma_tf32(float* c, const uint32_t* a, const uint32_t* b) {
    asm volatile(
        "mma.sync.aligned.m16n8k8.row.col.f32.tf32.tf32.f32 "
        "{%0,%1,%2,%3},{%4,%5,%6,%7},{%8,%9},{%0,%1,%2,%3};"
        : "+f"(c[0]), "+f"(c[1]), "+f"(c[2]), "+f"(c[3])
        : "r"(a[0]), "r"(a[1]), "r"(a[2]), "r"(a[3]), "r"(b[0]), "r"(b[1]));
}

__device__ __forceinline__ float sigmoidf_(float x) {
    return 1.f / (1.f + __expf(-x));
}

// ---------------- reset barrier counters -------------------------------------
__global__ void reset_kernel() {
    g_cnt[threadIdx.x >> 6][threadIdx.x & 63] = 0u;
}

// ---------------- prep 1: h0 = ELU(z @ W_init^T + b_init); g0 ---------------
__global__ void prep1_kernel(const float* __restrict__ z,
                             const float* __restrict__ Wi,
                             const float* __restrict__ bi,
                             const float* __restrict__ emb,
                             const float* __restrict__ Wih0,
                             const float* __restrict__ bih0) {
    int blk = blockIdx.x;
    int tid = threadIdx.x;   // 256
    if (blk < NB) {
        __shared__ float zs[NZ];
        if (tid < NZ) zs[tid] = z[blk * NZ + tid];
        __syncthreads();
        float acc = bi[tid];
        #pragma unroll 8
        for (int k = 0; k < NZ; k++) acc = fmaf(zs[k], Wi[tid * NZ + k], acc);
        float h = acc > 0.f ? acc : (expf(acc) - 1.f);
        g_h0[blk * NH + tid] = h;
        g_st0[0][blk * NH + tid] = h;
        g_st1[0][blk * NH + tid] = h;
    } else {
        __shared__ float es[NH];
        es[tid] = emb[tid];
        __syncthreads();
        int g = (blk - NB) * NH + tid;   // 3 blocks -> 768 outputs
        float acc = bih0[g];
        #pragma unroll 8
        for (int k = 0; k < NH; k++) acc = fmaf(es[k], Wih0[g * NH + k], acc);
        g_g0[g] = acc;
    }
}

// ---------------- persistent GRU layer kernel --------------------------------
// Grid (16, 8): blockIdx.x -> 32-batch tile, blockIdx.y -> 32-hidden tile.
// 256 threads = 8 warps: wm = warp&1 (16-row m tile), wn = warp>>2.. see below.
// Each warp computes a 16x8 hidden patch for ALL 3 gates -> gate math is
// register-local. Weights live in smem (tf32) for the whole kernel.
__global__ __launch_bounds__(256, 1) void gru_persist_kernel(
    int layer, const float* __restrict__ Whh, const float* __restrict__ bhh) {
    extern __shared__ float smem[];
    float* As = smem;                       // 32 x AS_STRIDE (tf32 h tile)
    float* Ws = smem + 32 * AS_STRIDE;      // 96 x WS_STRIDE (tf32 weights)

    const int tid = threadIdx.x;
    const int lane = tid & 31;
    const int warp = tid >> 5;
    const int wm = warp & 1;                // m half (16 rows)
    const int wn = warp >> 1;               // hidden n quarter (8 cols)
    const int bb0 = blockIdx.x * 32;        // batch tile base
    const int hj0 = blockIdx.y * 32;        // hidden tile base

    float* st[2];
    if (layer) { st[0] = g_st1[0]; st[1] = g_st1[1]; }
    else       { st[0] = g_st0[0]; st[1] = g_st0[1]; }
    float* ybase = layer ? g_y1 : g_y0;

    // ---- load weight slice once: rows = 3 gates x 32 hidden units ----
    #pragma unroll
    for (int i = 0; i < 24; i++) {
        int f = tid + i * 256;              // 0..6143 float4 tiles
        int rr = f >> 6;                    // 0..95
        int c4 = (f & 63) << 2;
        int gate = rr >> 5;
        int r = rr & 31;
        float4 v = *(const float4*)(Whh + (size_t)(gate * NH + hj0 + r) * NH + c4);
        float4 w;
        w.x = f2tf32(v.x); w.y = f2tf32(v.y); w.z = f2tf32(v.z); w.w = f2tf32(v.w);
        *(float4*)(Ws + rr * WS_STRIDE + c4) = w;
    }

    // per-thread fragment coordinates
    const int r0l = wm * 16 + (lane >> 2);      // local batch row (and +8)
    const int cl = wn * 8 + (lane & 3) * 2;     // local hidden col (2 cols)
    const int jg = hj0 + cl;                    // global hidden col

    // biases (constant across steps)
    const float2 br2 = *(const float2*)(bhh + jg);
    const float2 bz2 = *(const float2*)(bhh + NH + jg);
    const float2 bn2 = *(const float2*)(bhh + 2 * NH + jg);
    // layer0 constant input gates
    float2 x0r, x0z, x0n;
    if (!layer) {
        x0r = *(const float2*)(g_g0 + jg);
        x0z = *(const float2*)(g_g0 + NH + jg);
        x0n = *(const float2*)(g_g0 + 2 * NH + jg);
    }

    const float* aBase = As + (size_t)r0l * AS_STRIDE + (lane & 3);
    const float* bBase = Ws + (size_t)(wn * 8 + (lane >> 2)) * WS_STRIDE + (lane & 3);

    __syncthreads();

    for (int t = 0; t < NT; t++) {
        const float* hc = st[t & 1];
        float* hn_out = st[(t + 1) & 1];

        // ---- stage h tile (L2-coherent loads), convert to tf32 ----
        #pragma unroll
        for (int i = 0; i < 8; i++) {
            int f = tid + i * 256;          // 0..2047 float4 tiles
            int row = f >> 6;
            int c4 = (f & 63) << 2;
            float4 v = __ldcg((const float4*)(hc + (size_t)(bb0 + row) * NH + c4));
            float4 w;
            w.x = f2tf32(v.x); w.y = f2tf32(v.y); w.z = f2tf32(v.z); w.w = f2tf32(v.w);
            *(float4*)(As + row * AS_STRIDE + c4) = w;
        }
        __syncthreads();

        // ---- gh = h @ Whh^T for this (32 batch x 32 hidden x 3 gate) tile ----
        float acc[3][4];
        #pragma unroll
        for (int g = 0; g < 3; g++)
            #pragma unroll
            for (int c = 0; c < 4; c++) acc[g][c] = 0.f;

        #pragma unroll 8
        for (int k = 0; k < NH; k += 8) {
            uint32_t a[4], b[2];
            a[0] = __float_as_uint(aBase[k]);
            a[1] = __float_as_uint(aBase[8 * AS_STRIDE + k]);
            a[2] = __float_as_uint(aBase[k + 4]);
            a[3] = __float_as_uint(aBase[8 * AS_STRIDE + k + 4]);
            #pragma unroll
            for (int g = 0; g < 3; g++) {
                b[0] = __float_as_uint(bBase[g * 32 * WS_STRIDE + k]);
                b[1] = __float_as_uint(bBase[g * 32 * WS_STRIDE + k + 4]);
                mma_tf32(acc[g], a, b);
            }
        }

        // ---- gates + state update (register-local per thread) ----
        #pragma unroll
        for (int rr = 0; rr < 2; rr++) {
            int b = bb0 + r0l + rr * 8;
            float2 xr, xz, xn;
            if (!layer) { xr = x0r; xz = x0z; xn = x0n; }
            else {
                const float* gxp = g_gx1 + ((size_t)b * NT + t) * NG;
                xr = *(const float2*)(gxp + jg);
                xz = *(const float2*)(gxp + NH + jg);
                xn = *(const float2*)(gxp + 2 * NH + jg);
            }
            float2 hp = __ldcg((const float2*)(hc + (size_t)b * NH + jg));

            float r_0 = sigmoidf_(xr.x + acc[0][rr * 2 + 0] + br2.x);
            float r_1 = sigmoidf_(xr.y + acc[0][rr * 2 + 1] + br2.y);
            float u_0 = sigmoidf_(xz.x + acc[1][rr * 2 + 0] + bz2.x);
            float u_1 = sigmoidf_(xz.y + acc[1][rr * 2 + 1] + bz2.y);
            float n_0 = tanhf(xn.x + r_0 * (acc[2][rr * 2 + 0] + bn2.x));
            float n_1 = tanhf(xn.y + r_1 * (acc[2][rr * 2 + 1] + bn2.y));
            float2 hv;
            hv.x = (1.f - u_0) * n_0 + u_0 * hp.x;
            hv.y = (1.f - u_1) * n_1 + u_1 * hp.y;
            __stcg((float2*)(hn_out + (size_t)b * NH + jg), hv);
            *(float2*)(ybase + ((size_t)b * NT + t) * NH + jg) = hv;
        }

        // ---- grid barrier: all blocks must finish step t before t+1 ----
        __threadfence();
        __syncthreads();
        if (tid == 0) {
            atomicAdd(&g_cnt[layer][t], 1u);
            volatile unsigned* p = &g_cnt[layer][t];
            while (*p < NBLK) { }
        }
        __syncthreads();
    }
}

// ---------------- LayerNorm + ELU (one row per block, 256 threads) -----------
__global__ void ln_elu_kernel(const float* __restrict__ gam,
                              const float* __restrict__ bet) {
    int row = blockIdx.x;
    int tid = threadIdx.x;
    float v = g_y1[(size_t)row * NH + tid];

    __shared__ float red[8];
    float s = v;
    #pragma unroll
    for (int o = 16; o; o >>= 1) s += __shfl_xor_sync(0xffffffffu, s, o);
    if ((tid & 31) == 0) red[tid >> 5] = s;
    __syncthreads();
    float tot = red[0] + red[1] + red[2] + red[3] + red[4] + red[5] + red[6] + red[7];
    float mu = tot * (1.f / NH);
    __syncthreads();

    float d = v - mu;
    s = d * d;
    #pragma unroll
    for (int o = 16; o; o >>= 1) s += __shfl_xor_sync(0xffffffffu, s, o);
    if ((tid & 31) == 0) red[tid >> 5] = s;
    __syncthreads();
    tot = red[0] + red[1] + red[2] + red[3] + red[4] + red[5] + red[6] + red[7];
    float var = tot * (1.f / NH);

    float yv = d * rsqrtf(var + 1e-5f) * gam[tid] + bet[tid];
    yv = yv > 0.f ? yv : (__expf(yv) - 1.f);
    g_act[(size_t)row * NH + tid] = yv;
}

// ---------------- tf32 GEMM: C = A(M x 256) * Bm(N x 256)^T + bias -----------
__global__ __launch_bounds__(256) void gemm_tf32_kernel(
    int which, const float* __restrict__ Bm, const float* __restrict__ bias,
    float* __restrict__ Cout, int N) {
    const int K = NH;  // 256
    const float* A = which ? g_act : g_y0;
    float* C = which ? Cout : g_gx1;

    __shared__ float As[128 * 36];
    __shared__ float Bs[128 * 36];

    int tid = threadIdx.x;
    int lane = tid & 31;
    int warp = tid >> 5;
    int wm = warp & 1;
    int wn = warp >> 1;
    int m0 = blockIdx.y * 128;
    int n0 = blockIdx.x * 128;

    float acc[4][4][4];
    #pragma unroll
    for (int a = 0; a < 4; a++)
        #pragma unroll
        for (int b = 0; b < 4; b++)
            #pragma unroll
            for (int c = 0; c < 4; c++) acc[a][b][c] = 0.f;

    for (int kt = 0; kt < K; kt += 32) {
        #pragma unroll
        for (int i = 0; i < 4; i++) {
            int f = i * 256 + tid;        // 1024 float4 tiles
            int r = f >> 3;
            int c = (f & 7) << 2;
            float4 va = *(const float4*)(A + (size_t)(m0 + r) * K + kt + c);
            float* da = &As[r * 36 + c];
            da[0] = f2tf32(va.x); da[1] = f2tf32(va.y);
            da[2] = f2tf32(va.z); da[3] = f2tf32(va.w);

            int n = n0 + r;
            float4 vb = make_float4(0.f, 0.f, 0.f, 0.f);
            if (n < N) vb = *(const float4*)(Bm + (size_t)n * K + kt + c);
            float* db = &Bs[r * 36 + c];
            db[0] = f2tf32(vb.x); db[1] = f2tf32(vb.y);
            db[2] = f2tf32(vb.z); db[3] = f2tf32(vb.w);
        }
        __syncthreads();

        #pragma unroll
        for (int kk = 0; kk < 4; kk++) {
            int kb = kk * 8;
            uint32_t af[4][4];
            uint32_t bf[4][2];
            int ra = wm * 64 + (lane >> 2);
            int ca = kb + (lane & 3);
            #pragma unroll
            for (int mf = 0; mf < 4; mf++) {
                const float* p = &As[(ra + mf * 16) * 36 + ca];
                af[mf][0] = __float_as_uint(p[0]);
                af[mf][1] = __float_as_uint(p[8 * 36]);
                af[mf][2] = __float_as_uint(p[4]);
                af[mf][3] = __float_as_uint(p[8 * 36 + 4]);
            }
            int rb = wn * 32 + (lane >> 2);
            #pragma unroll
            for (int nf = 0; nf < 4; nf++) {
                const float* p = &Bs[(rb + nf * 8) * 36 + ca];
                bf[nf][0] = __float_as_uint(p[0]);
                bf[nf][1] = __float_as_uint(p[4]);
            }
            #pragma unroll
            for (int mf = 0; mf < 4; mf++)
                #pragma unroll
                for (int nf = 0; nf < 4; nf++)
                    mma_tf32(acc[mf][nf], af[mf], bf[nf]);
        }
        __syncthreads();
    }

    // epilogue: add bias, store
    #pragma unroll
    for (int mf = 0; mf < 4; mf++) {
        int row = m0 + wm * 64 + mf * 16 + (lane >> 2);
        #pragma unroll
        for (int nf = 0; nf < 4; nf++) {
            int col = n0 + wn * 32 + nf * 8 + (lane & 3) * 2;
            if (col < N) {
                float2 bv = *(const float2*)(bias + col);
                float2 o0 = make_float2(acc[mf][nf][0] + bv.x, acc[mf][nf][1] + bv.y);
                float2 o1 = make_float2(acc[mf][nf][2] + bv.x, acc[mf][nf][3] + bv.y);
                *(float2*)(C + (size_t)row * N + col) = o0;
                *(float2*)(C + (size_t)(row + 8) * N + col) = o1;
            }
        }
    }
}

// ---------------- launch -----------------------------------------------------
extern "C" void kernel_launch(void* const* d_in, const int* in_sizes, int n_in,
                              void* d_out, int out_size) {
    const float* z      = (const float*)d_in[0];
    const float* W_init = (const float*)d_in[1];
    const float* b_init = (const float*)d_in[2];
    const float* emb    = (const float*)d_in[3];
    const float* W_ih0  = (const float*)d_in[4];
    const float* b_ih0  = (const float*)d_in[6];
    const float* W_hh0  = (const float*)d_in[5];
    const float* b_hh0  = (const float*)d_in[7];
    const float* W_ih1  = (const float*)d_in[8];
    const float* W_hh1  = (const float*)d_in[9];
    const float* b_ih1  = (const float*)d_in[10];
    const float* b_hh1  = (const float*)d_in[11];
    const float* ln_g   = (const float*)d_in[12];
    const float* ln_b   = (const float*)d_in[13];
    const float* W_out  = (const float*)d_in[14];
    const float* b_out  = (const float*)d_in[15];
    float* out = (float*)d_out;

    static bool attr_done = false;
    if (!attr_done) {
        cudaFuncSetAttribute(gru_persist_kernel,
                             cudaFuncAttributeMaxDynamicSharedMemorySize, GRU_SMEM);
        attr_done = true;
    }

    // reset barrier counters + init h0/g0
    reset_kernel<<<1, 128>>>();
    prep1_kernel<<<NB + 3, 256>>>(z, W_init, b_init, emb, W_ih0, b_ih0);

    // GRU layer 0 (persistent; input gates are the constant g0)
    gru_persist_kernel<<<dim3(16, 8), 256, GRU_SMEM>>>(0, W_hh0, b_hh0);

    // layer-1 input gates for all timesteps: gx1 = Y0 @ W_ih1^T + b_ih1
    gemm_tf32_kernel<<<dim3(NG / 128, MTOT / 128), 256>>>(0, W_ih1, b_ih1, nullptr, NG);

    // GRU layer 1 (persistent)
    gru_persist_kernel<<<dim3(16, 8), 256, GRU_SMEM>>>(1, W_hh1, b_hh1);

    // LayerNorm + ELU
    ln_elu_kernel<<<MTOT, 256>>>(ln_g, ln_b);

    // logits = act @ W_out^T + b_out
    gemm_tf32_kernel<<<dim3((NP + 127) / 128, MTOT / 128), 256>>>(1, W_out, b_out, out, NP);
}

// round 6
// speedup vs baseline: 3.0600x; 1.1170x over previous
#include <cuda_runtime.h>
#include <cstdint>
#include <math.h>

// Problem dims
#define NB 512
#define NZ 64
#define NH 256
#define NG 768   // 3*H
#define NT 64
#define NP 10000
#define NPAD 10112          // NP padded to 128
#define MTOT (NB * NT)      // 32768

#define NBLK 128            // persistent GRU grid
#define AS_STRIDE 268
#define WS_STRIDE 260
#define GRU_SMEM ((32 * AS_STRIDE + 96 * WS_STRIDE) * 4)

// GEMM tiling
#define GS 36               // smem row stride (floats) for 32-wide K tile
#define GEMM_SMEM (2 * 2 * 128 * GS * 4)   // 2 stages x (A+B) x 128 rows

// ---------------- scratch (device globals; no allocations allowed) ----------
__device__ float g_h0[NB * NH];
__device__ float g_g0[NG];
__device__ float g_st0[2][NB * NH];
__device__ float g_st1[2][NB * NH];
__device__ float g_y0[MTOT * NH];            // layer0 outputs, tf32-rounded
__device__ float g_gx1[(size_t)MTOT * NG];
__device__ float g_y1[MTOT * NH];            // layer1 outputs (fp32, pre-LN)
__device__ float g_act[MTOT * NH];           // post LN+ELU, tf32-rounded
__device__ float g_Wih1c[NG * NH];           // tf32 copy of W_ih1
__device__ float g_Woutc[NPAD * NH];         // tf32 copy of W_out, zero padded
__device__ unsigned g_cnt[2][NT];

// ---------------- helpers ----------------------------------------------------
__device__ __forceinline__ float f2tf32(float f) {
    uint32_t u;
    asm("cvt.rna.tf32.f32 %0, %1;" : "=r"(u) : "f"(f));
    return __uint_as_float(u);
}

__device__ __forceinline__ void mma_tf32(float* c, const uint32_t* a, const uint32_t* b) {
    asm volatile(
        "mma.sync.aligned.m16n8k8.row.col.f32.tf32.tf32.f32 "
        "{%0,%1,%2,%3},{%4,%5,%6,%7},{%8,%9},{%0,%1,%2,%3};"
        : "+f"(c[0]), "+f"(c[1]), "+f"(c[2]), "+f"(c[3])
        : "r"(a[0]), "r"(a[1]), "r"(a[2]), "r"(a[3]), "r"(b[0]), "r"(b[1]));
}

__device__ __forceinline__ float sigmoidf_(float x) {
    return 1.f / (1.f + __expf(-x));
}

__device__ __forceinline__ void cp_async16(void* smem_dst, const void* gsrc) {
    unsigned a = (unsigned)__cvta_generic_to_shared(smem_dst);
    asm volatile("cp.async.cg.shared.global [%0], [%1], 16;" :: "r"(a), "l"(gsrc));
}

// ---------------- reset barrier counters -------------------------------------
__global__ void reset_kernel() {
    g_cnt[threadIdx.x >> 6][threadIdx.x & 63] = 0u;
}

// ---------------- prep 1: h0 = ELU(z @ W_init^T + b_init); g0 ---------------
__global__ void prep1_kernel(const float* __restrict__ z,
                             const float* __restrict__ Wi,
                             const float* __restrict__ bi,
                             const float* __restrict__ emb,
                             const float* __restrict__ Wih0,
                             const float* __restrict__ bih0) {
    int blk = blockIdx.x;
    int tid = threadIdx.x;   // 256
    if (blk < NB) {
        __shared__ float zs[NZ];
        if (tid < NZ) zs[tid] = z[blk * NZ + tid];
        __syncthreads();
        float acc = bi[tid];
        #pragma unroll 8
        for (int k = 0; k < NZ; k++) acc = fmaf(zs[k], Wi[tid * NZ + k], acc);
        float h = acc > 0.f ? acc : (expf(acc) - 1.f);
        g_h0[blk * NH + tid] = h;
        g_st0[0][blk * NH + tid] = h;
        g_st1[0][blk * NH + tid] = h;
    } else {
        __shared__ float es[NH];
        es[tid] = emb[tid];
        __syncthreads();
        int g = (blk - NB) * NH + tid;
        float acc = bih0[g];
        #pragma unroll 8
        for (int k = 0; k < NH; k++) acc = fmaf(es[k], Wih0[g * NH + k], acc);
        g_g0[g] = acc;
    }
}

// ---------------- prep: tf32 conversions of B matrices -----------------------
__global__ void convw_kernel(const float* __restrict__ Wih1,
                             const float* __restrict__ Wout) {
    int idx = blockIdx.x * blockDim.x + threadIdx.x;
    const int n1 = NG * NH;
    const int n2 = NPAD * NH;
    if (idx < n1) {
        g_Wih1c[idx] = f2tf32(Wih1[idx]);
    }
    for (int j = idx; j < n2; j += gridDim.x * blockDim.x) {
        int row = j >> 8;
        g_Woutc[j] = (row < NP) ? f2tf32(Wout[j]) : 0.f;
    }
}

// ---------------- persistent GRU layer kernel --------------------------------
__global__ __launch_bounds__(256, 1) void gru_persist_kernel(
    int layer, const float* __restrict__ Whh, const float* __restrict__ bhh) {
    extern __shared__ float smem[];
    float* As = smem;
    float* Ws = smem + 32 * AS_STRIDE;

    const int tid = threadIdx.x;
    const int lane = tid & 31;
    const int warp = tid >> 5;
    const int wm = warp & 1;
    const int wn = warp >> 1;
    const int bb0 = blockIdx.x * 32;
    const int hj0 = blockIdx.y * 32;

    float* st[2];
    if (layer) { st[0] = g_st1[0]; st[1] = g_st1[1]; }
    else       { st[0] = g_st0[0]; st[1] = g_st0[1]; }
    float* ybase = layer ? g_y1 : g_y0;

    #pragma unroll
    for (int i = 0; i < 24; i++) {
        int f = tid + i * 256;
        int rr = f >> 6;
        int c4 = (f & 63) << 2;
        int gate = rr >> 5;
        int r = rr & 31;
        float4 v = *(const float4*)(Whh + (size_t)(gate * NH + hj0 + r) * NH + c4);
        float4 w;
        w.x = f2tf32(v.x); w.y = f2tf32(v.y); w.z = f2tf32(v.z); w.w = f2tf32(v.w);
        *(float4*)(Ws + rr * WS_STRIDE + c4) = w;
    }

    const int r0l = wm * 16 + (lane >> 2);
    const int cl = wn * 8 + (lane & 3) * 2;
    const int jg = hj0 + cl;

    const float2 br2 = *(const float2*)(bhh + jg);
    const float2 bz2 = *(const float2*)(bhh + NH + jg);
    const float2 bn2 = *(const float2*)(bhh + 2 * NH + jg);
    float2 x0r, x0z, x0n;
    if (!layer) {
        x0r = *(const float2*)(g_g0 + jg);
        x0z = *(const float2*)(g_g0 + NH + jg);
        x0n = *(const float2*)(g_g0 + 2 * NH + jg);
    }

    const float* aBase = As + (size_t)r0l * AS_STRIDE + (lane & 3);
    const float* bBase = Ws + (size_t)(wn * 8 + (lane >> 2)) * WS_STRIDE + (lane & 3);

    __syncthreads();

    for (int t = 0; t < NT; t++) {
        const float* hc = st[t & 1];
        float* hn_out = st[(t + 1) & 1];

        #pragma unroll
        for (int i = 0; i < 8; i++) {
            int f = tid + i * 256;
            int row = f >> 6;
            int c4 = (f & 63) << 2;
            float4 v = __ldcg((const float4*)(hc + (size_t)(bb0 + row) * NH + c4));
            float4 w;
            w.x = f2tf32(v.x); w.y = f2tf32(v.y); w.z = f2tf32(v.z); w.w = f2tf32(v.w);
            *(float4*)(As + row * AS_STRIDE + c4) = w;
        }
        __syncthreads();

        float acc[3][4];
        #pragma unroll
        for (int g = 0; g < 3; g++)
            #pragma unroll
            for (int c = 0; c < 4; c++) acc[g][c] = 0.f;

        #pragma unroll 8
        for (int k = 0; k < NH; k += 8) {
            uint32_t a[4], b[2];
            a[0] = __float_as_uint(aBase[k]);
            a[1] = __float_as_uint(aBase[8 * AS_STRIDE + k]);
            a[2] = __float_as_uint(aBase[k + 4]);
            a[3] = __float_as_uint(aBase[8 * AS_STRIDE + k + 4]);
            #pragma unroll
            for (int g = 0; g < 3; g++) {
                b[0] = __float_as_uint(bBase[g * 32 * WS_STRIDE + k]);
                b[1] = __float_as_uint(bBase[g * 32 * WS_STRIDE + k + 4]);
                mma_tf32(acc[g], a, b);
            }
        }

        #pragma unroll
        for (int rr = 0; rr < 2; rr++) {
            int b = bb0 + r0l + rr * 8;
            float2 xr, xz, xn;
            if (!layer) { xr = x0r; xz = x0z; xn = x0n; }
            else {
                const float* gxp = g_gx1 + ((size_t)b * NT + t) * NG;
                xr = *(const float2*)(gxp + jg);
                xz = *(const float2*)(gxp + NH + jg);
                xn = *(const float2*)(gxp + 2 * NH + jg);
            }
            float2 hp = __ldcg((const float2*)(hc + (size_t)b * NH + jg));

            float r_0 = sigmoidf_(xr.x + acc[0][rr * 2 + 0] + br2.x);
            float r_1 = sigmoidf_(xr.y + acc[0][rr * 2 + 1] + br2.y);
            float u_0 = sigmoidf_(xz.x + acc[1][rr * 2 + 0] + bz2.x);
            float u_1 = sigmoidf_(xz.y + acc[1][rr * 2 + 1] + bz2.y);
            float n_0 = tanhf(xn.x + r_0 * (acc[2][rr * 2 + 0] + bn2.x));
            float n_1 = tanhf(xn.y + r_1 * (acc[2][rr * 2 + 1] + bn2.y));
            float2 hv;
            hv.x = (1.f - u_0) * n_0 + u_0 * hp.x;
            hv.y = (1.f - u_1) * n_1 + u_1 * hp.y;
            __stcg((float2*)(hn_out + (size_t)b * NH + jg), hv);
            float2 yv = hv;
            if (!layer) { yv.x = f2tf32(hv.x); yv.y = f2tf32(hv.y); }
            *(float2*)(ybase + ((size_t)b * NT + t) * NH + jg) = yv;
        }

        __threadfence();
        __syncthreads();
        if (tid == 0) {
            atomicAdd(&g_cnt[layer][t], 1u);
            volatile unsigned* p = &g_cnt[layer][t];
            while (*p < NBLK) { }
        }
        __syncthreads();
    }
}

// ---------------- LayerNorm + ELU (writes tf32-rounded activations) ----------
__global__ void ln_elu_kernel(const float* __restrict__ gam,
                              const float* __restrict__ bet) {
    int row = blockIdx.x;
    int tid = threadIdx.x;
    float v = g_y1[(size_t)row * NH + tid];

    __shared__ float red[8];
    float s = v;
    #pragma unroll
    for (int o = 16; o; o >>= 1) s += __shfl_xor_sync(0xffffffffu, s, o);
    if ((tid & 31) == 0) red[tid >> 5] = s;
    __syncthreads();
    float tot = red[0] + red[1] + red[2] + red[3] + red[4] + red[5] + red[6] + red[7];
    float mu = tot * (1.f / NH);
    __syncthreads();

    float d = v - mu;
    s = d * d;
    #pragma unroll
    for (int o = 16; o; o >>= 1) s += __shfl_xor_sync(0xffffffffu, s, o);
    if ((tid & 31) == 0) red[tid >> 5] = s;
    __syncthreads();
    tot = red[0] + red[1] + red[2] + red[3] + red[4] + red[5] + red[6] + red[7];
    float var = tot * (1.f / NH);

    float yv = d * rsqrtf(var + 1e-5f) * gam[tid] + bet[tid];
    yv = yv > 0.f ? yv : (__expf(yv) - 1.f);
    g_act[(size_t)row * NH + tid] = f2tf32(yv);
}

// ---------------- pipelined tf32 GEMM: C = A * B^T + bias --------------------
// A: M x 256 (tf32-rounded), B: Npad x 256 (tf32-rounded, padded), C guarded
// by col < Nstore. 2-stage cp.async pipeline, tile 128x128xK32, 256 threads.
__global__ __launch_bounds__(256, 2) void gemm_pipe_kernel(
    const float* __restrict__ A, const float* __restrict__ Bm,
    const float* __restrict__ bias, float* __restrict__ C, int Nstore) {
    const int K = NH;
    extern __shared__ float sm[];
    // layout: [stage][A/B][128*GS]
    float* sA[2] = { sm,                sm + 2 * 128 * GS };
    float* sB[2] = { sm + 128 * GS,     sm + 3 * 128 * GS };

    const int tid = threadIdx.x;
    const int lane = tid & 31;
    const int warp = tid >> 5;
    const int wm = warp & 1;
    const int wn = warp >> 1;
    const int m0 = blockIdx.y * 128;
    const int n0 = blockIdx.x * 128;

    // per-thread staging coords (4 float4 each for A and B)
    const int sr = tid >> 3;            // 0..31 base row, +32 per i
    const int sc = (tid & 7) << 2;      // 0,4,..,28

    float acc[4][4][4];
    #pragma unroll
    for (int a = 0; a < 4; a++)
        #pragma unroll
        for (int b = 0; b < 4; b++)
            #pragma unroll
            for (int c = 0; c < 4; c++) acc[a][b][c] = 0.f;

    // prologue: stage k-tile 0 into buffer 0
    #pragma unroll
    for (int i = 0; i < 4; i++) {
        int r = sr + i * 32;
        cp_async16(sA[0] + r * GS + sc, A + (size_t)(m0 + r) * K + sc);
        cp_async16(sB[0] + r * GS + sc, Bm + (size_t)(n0 + r) * K + sc);
    }
    asm volatile("cp.async.commit_group;");

    const float* aBase0 = (float*)nullptr;
    const int ra = wm * 64 + (lane >> 2);
    const int rb = wn * 32 + (lane >> 2);
    const int ca = lane & 3;

    #pragma unroll
    for (int kt = 0; kt < 8; kt++) {
        const int buf = kt & 1;
        if (kt + 1 < 8) {
            const int nb = buf ^ 1;
            const int ko = (kt + 1) * 32;
            #pragma unroll
            for (int i = 0; i < 4; i++) {
                int r = sr + i * 32;
                cp_async16(sA[nb] + r * GS + sc, A + (size_t)(m0 + r) * K + ko + sc);
                cp_async16(sB[nb] + r * GS + sc, Bm + (size_t)(n0 + r) * K + ko + sc);
            }
            asm volatile("cp.async.commit_group;");
            asm volatile("cp.async.wait_group 1;");
        } else {
            asm volatile("cp.async.wait_group 0;");
        }
        __syncthreads();

        const float* aB = sA[buf] + (size_t)ra * GS + ca;
        const float* bB = sB[buf] + (size_t)rb * GS + ca;
        #pragma unroll
        for (int kk = 0; kk < 4; kk++) {
            const int kb = kk * 8;
            uint32_t af[4][4];
            uint32_t bf[4][2];
            #pragma unroll
            for (int mf = 0; mf < 4; mf++) {
                const float* p = aB + (size_t)mf * 16 * GS + kb;
                af[mf][0] = __float_as_uint(p[0]);
                af[mf][1] = __float_as_uint(p[8 * GS]);
                af[mf][2] = __float_as_uint(p[4]);
                af[mf][3] = __float_as_uint(p[8 * GS + 4]);
            }
            #pragma unroll
            for (int nf = 0; nf < 4; nf++) {
                const float* p = bB + (size_t)nf * 8 * GS + kb;
                bf[nf][0] = __float_as_uint(p[0]);
                bf[nf][1] = __float_as_uint(p[4]);
            }
            #pragma unroll
            for (int mf = 0; mf < 4; mf++)
                #pragma unroll
                for (int nf = 0; nf < 4; nf++)
                    mma_tf32(acc[mf][nf], af[mf], bf[nf]);
        }
        __syncthreads();
    }
    (void)aBase0;

    // epilogue: add bias, store (guard col < Nstore)
    #pragma unroll
    for (int mf = 0; mf < 4; mf++) {
        int row = m0 + wm * 64 + mf * 16 + (lane >> 2);
        #pragma unroll
        for (int nf = 0; nf < 4; nf++) {
            int col = n0 + wn * 32 + nf * 8 + (lane & 3) * 2;
            if (col < Nstore) {
                float2 bv = *(const float2*)(bias + col);
                float2 o0 = make_float2(acc[mf][nf][0] + bv.x, acc[mf][nf][1] + bv.y);
                float2 o1 = make_float2(acc[mf][nf][2] + bv.x, acc[mf][nf][3] + bv.y);
                *(float2*)(C + (size_t)row * Nstore + col) = o0;
                *(float2*)(C + (size_t)(row + 8) * Nstore + col) = o1;
            }
        }
    }
}

// ---------------- launch -----------------------------------------------------
extern "C" void kernel_launch(void* const* d_in, const int* in_sizes, int n_in,
                              void* d_out, int out_size) {
    const float* z      = (const float*)d_in[0];
    const float* W_init = (const float*)d_in[1];
    const float* b_init = (const float*)d_in[2];
    const float* emb    = (const float*)d_in[3];
    const float* W_ih0  = (const float*)d_in[4];
    const float* W_hh0  = (const float*)d_in[5];
    const float* b_ih0  = (const float*)d_in[6];
    const float* b_hh0  = (const float*)d_in[7];
    const float* W_ih1  = (const float*)d_in[8];
    const float* W_hh1  = (const float*)d_in[9];
    const float* b_ih1  = (const float*)d_in[10];
    const float* b_hh1  = (const float*)d_in[11];
    const float* ln_g   = (const float*)d_in[12];
    const float* ln_b   = (const float*)d_in[13];
    const float* W_out  = (const float*)d_in[14];
    const float* b_out  = (const float*)d_in[15];
    float* out = (float*)d_out;

    static bool attr_done = false;
    if (!attr_done) {
        cudaFuncSetAttribute(gru_persist_kernel,
                             cudaFuncAttributeMaxDynamicSharedMemorySize, GRU_SMEM);
        cudaFuncSetAttribute(gemm_pipe_kernel,
                             cudaFuncAttributeMaxDynamicSharedMemorySize, GEMM_SMEM);
        attr_done = true;
    }

    float* Wih1c; cudaGetSymbolAddress((void**)&Wih1c, g_Wih1c);
    float* Woutc; cudaGetSymbolAddress((void**)&Woutc, g_Woutc);
    float* y0;    cudaGetSymbolAddress((void**)&y0, g_y0);
    float* act;   cudaGetSymbolAddress((void**)&act, g_act);
    float* gx1;   cudaGetSymbolAddress((void**)&gx1, g_gx1);

    reset_kernel<<<1, 128>>>();
    prep1_kernel<<<NB + 3, 256>>>(z, W_init, b_init, emb, W_ih0, b_ih0);
    convw_kernel<<<2720, 256>>>(W_ih1, W_out);

    // GRU layer 0 (persistent)
    gru_persist_kernel<<<dim3(16, 8), 256, GRU_SMEM>>>(0, W_hh0, b_hh0);

    // gx1 = Y0 @ W_ih1^T + b_ih1
    gemm_pipe_kernel<<<dim3(NG / 128, MTOT / 128), 256, GEMM_SMEM>>>(
        y0, Wih1c, b_ih1, gx1, NG);

    // GRU layer 1 (persistent)
    gru_persist_kernel<<<dim3(16, 8), 256, GRU_SMEM>>>(1, W_hh1, b_hh1);

    // LayerNorm + ELU
    ln_elu_kernel<<<MTOT, 256>>>(ln_g, ln_b);

    // logits = act @ W_out^T + b_out
    gemm_pipe_kernel<<<dim3(NPAD / 128, MTOT / 128), 256, GEMM_SMEM>>>(
        act, Woutc, b_out, out, NP);
}

// round 7
// speedup vs baseline: 3.3107x; 1.0819x over previous
#include <cuda_runtime.h>
#include <cstdint>
#include <math.h>

// Problem dims
#define NB 512
#define NZ 64
#define NH 256
#define NG 768   // 3*H
#define NT 64
#define NP 10000
#define NPAD 10112          // NP padded to 128
#define MTOT (NB * NT)      // 32768

#define AS_STRIDE 268
#define WS_STRIDE 260
#define GRU_SMEM ((32 * AS_STRIDE + 96 * WS_STRIDE) * 4)

// GEMM: swizzled GS=32 layout, 2 stages
#define GEMM_SMEM (2 * 2 * 128 * 32 * 4)   // 64 KB

// ---------------- scratch (device globals; no allocations allowed) ----------
__device__ float g_h0[NB * NH];
__device__ float g_g0[NG];
__device__ float g_st0[2][NB * NH];
__device__ float g_st1[2][NB * NH];
__device__ float g_y0[MTOT * NH];            // layer0 outputs, tf32, K-permuted
__device__ float g_gx1[(size_t)MTOT * NG];
__device__ float g_y1[MTOT * NH];            // layer1 outputs (fp32, pre-LN)
__device__ float g_act[MTOT * NH];           // post LN+ELU, tf32, K-permuted
__device__ float g_Wih1c[NG * NH];           // tf32, K-permuted
__device__ float g_Woutc[NPAD * NH];         // tf32, K-permuted, zero padded
__device__ unsigned g_cnt2[2][NT][16];       // per-(layer,t,batch-tile) barrier

// ---------------- helpers ----------------------------------------------------
__device__ __forceinline__ float f2tf32(float f) {
    uint32_t u;
    asm("cvt.rna.tf32.f32 %0, %1;" : "=r"(u) : "f"(f));
    return __uint_as_float(u);
}

// K permutation: within each 16-block, p = 4*(k%4) + (k%16)/4
__device__ __forceinline__ int kperm(int k) {
    return (k & ~15) | ((k & 3) << 2) | ((k >> 2) & 3);
}

__device__ __forceinline__ void mma_tf32(float* c, const uint32_t* a, const uint32_t* b) {
    asm volatile(
        "mma.sync.aligned.m16n8k8.row.col.f32.tf32.tf32.f32 "
        "{%0,%1,%2,%3},{%4,%5,%6,%7},{%8,%9},{%0,%1,%2,%3};"
        : "+f"(c[0]), "+f"(c[1]), "+f"(c[2]), "+f"(c[3])
        : "r"(a[0]), "r"(a[1]), "r"(a[2]), "r"(a[3]), "r"(b[0]), "r"(b[1]));
}

__device__ __forceinline__ float sigmoidf_(float x) {
    return 1.f / (1.f + __expf(-x));
}

__device__ __forceinline__ void cp_async16(void* smem_dst, const void* gsrc) {
    unsigned a = (unsigned)__cvta_generic_to_shared(smem_dst);
    asm volatile("cp.async.cg.shared.global [%0], [%1], 16;" :: "r"(a), "l"(gsrc));
}

// ---------------- reset barrier counters -------------------------------------
__global__ void reset_kernel() {
    int i = blockIdx.x * blockDim.x + threadIdx.x;   // 2*64*16 = 2048
    ((unsigned*)g_cnt2)[i] = 0u;
}

// ---------------- prep 1: h0 = ELU(z @ W_init^T + b_init); g0 ---------------
__global__ void prep1_kernel(const float* __restrict__ z,
                             const float* __restrict__ Wi,
                             const float* __restrict__ bi,
                             const float* __restrict__ emb,
                             const float* __restrict__ Wih0,
                             const float* __restrict__ bih0) {
    int blk = blockIdx.x;
    int tid = threadIdx.x;   // 256
    if (blk < NB) {
        __shared__ float zs[NZ];
        if (tid < NZ) zs[tid] = z[blk * NZ + tid];
        __syncthreads();
        float acc = bi[tid];
        #pragma unroll 8
        for (int k = 0; k < NZ; k++) acc = fmaf(zs[k], Wi[tid * NZ + k], acc);
        float h = acc > 0.f ? acc : (expf(acc) - 1.f);
        g_h0[blk * NH + tid] = h;
        g_st0[0][blk * NH + tid] = h;
        g_st1[0][blk * NH + tid] = h;
    } else {
        __shared__ float es[NH];
        es[tid] = emb[tid];
        __syncthreads();
        int g = (blk - NB) * NH + tid;
        float acc = bih0[g];
        #pragma unroll 8
        for (int k = 0; k < NH; k++) acc = fmaf(es[k], Wih0[g * NH + k], acc);
        g_g0[g] = acc;
    }
}

// ---------------- prep: tf32 + K-permuted copies of B matrices ---------------
__global__ void convw_kernel(const float* __restrict__ Wih1,
                             const float* __restrict__ Wout) {
    int idx = blockIdx.x * blockDim.x + threadIdx.x;
    const int n1 = NG * NH;
    const int n2 = NPAD * NH;
    if (idx < n1) {
        int row = idx >> 8, col = idx & 255;
        g_Wih1c[(row << 8) | kperm(col)] = f2tf32(Wih1[idx]);
    }
    for (int j = idx; j < n2; j += gridDim.x * blockDim.x) {
        int row = j >> 8, col = j & 255;
        g_Woutc[(row << 8) | kperm(col)] = (row < NP) ? f2tf32(Wout[j]) : 0.f;
    }
}

// ---------------- persistent GRU layer kernel --------------------------------
__global__ __launch_bounds__(256, 1) void gru_persist_kernel(
    int layer, const float* __restrict__ Whh, const float* __restrict__ bhh) {
    extern __shared__ float smem[];
    float* As = smem;
    float* Ws = smem + 32 * AS_STRIDE;

    const int tid = threadIdx.x;
    const int lane = tid & 31;
    const int warp = tid >> 5;
    const int wm = warp & 1;
    const int wn = warp >> 1;
    const int bb0 = blockIdx.x * 32;
    const int hj0 = blockIdx.y * 32;

    float* st[2];
    if (layer) { st[0] = g_st1[0]; st[1] = g_st1[1]; }
    else       { st[0] = g_st0[0]; st[1] = g_st0[1]; }
    float* ybase = layer ? g_y1 : g_y0;

    #pragma unroll
    for (int i = 0; i < 24; i++) {
        int f = tid + i * 256;
        int rr = f >> 6;
        int c4 = (f & 63) << 2;
        int gate = rr >> 5;
        int r = rr & 31;
        float4 v = *(const float4*)(Whh + (size_t)(gate * NH + hj0 + r) * NH + c4);
        float4 w;
        w.x = f2tf32(v.x); w.y = f2tf32(v.y); w.z = f2tf32(v.z); w.w = f2tf32(v.w);
        *(float4*)(Ws + rr * WS_STRIDE + c4) = w;
    }

    const int r0l = wm * 16 + (lane >> 2);
    const int cl = wn * 8 + (lane & 3) * 2;
    const int jg = hj0 + cl;
    const int p0 = kperm(jg) - hj0 - (hj0 ? 0 : 0);   // global permuted cols
    const int pj0 = kperm(jg);
    const int pj1 = kperm(jg + 1);

    const float2 br2 = *(const float2*)(bhh + jg);
    const float2 bz2 = *(const float2*)(bhh + NH + jg);
    const float2 bn2 = *(const float2*)(bhh + 2 * NH + jg);
    float2 x0r, x0z, x0n;
    if (!layer) {
        x0r = *(const float2*)(g_g0 + jg);
        x0z = *(const float2*)(g_g0 + NH + jg);
        x0n = *(const float2*)(g_g0 + 2 * NH + jg);
    }

    const float* aBase = As + (size_t)r0l * AS_STRIDE + (lane & 3);
    const float* bBase = Ws + (size_t)(wn * 8 + (lane >> 2)) * WS_STRIDE + (lane & 3);
    (void)p0;

    __syncthreads();

    for (int t = 0; t < NT; t++) {
        const float* hc = st[t & 1];
        float* hn_out = st[(t + 1) & 1];

        #pragma unroll
        for (int i = 0; i < 8; i++) {
            int f = tid + i * 256;
            int row = f >> 6;
            int c4 = (f & 63) << 2;
            float4 v = __ldcg((const float4*)(hc + (size_t)(bb0 + row) * NH + c4));
            float4 w;
            w.x = f2tf32(v.x); w.y = f2tf32(v.y); w.z = f2tf32(v.z); w.w = f2tf32(v.w);
            *(float4*)(As + row * AS_STRIDE + c4) = w;
        }
        __syncthreads();

        float acc[3][4];
        #pragma unroll
        for (int g = 0; g < 3; g++)
            #pragma unroll
            for (int c = 0; c < 4; c++) acc[g][c] = 0.f;

        #pragma unroll 8
        for (int k = 0; k < NH; k += 8) {
            uint32_t a[4], b[2];
            a[0] = __float_as_uint(aBase[k]);
            a[1] = __float_as_uint(aBase[8 * AS_STRIDE + k]);
            a[2] = __float_as_uint(aBase[k + 4]);
            a[3] = __float_as_uint(aBase[8 * AS_STRIDE + k + 4]);
            #pragma unroll
            for (int g = 0; g < 3; g++) {
                b[0] = __float_as_uint(bBase[g * 32 * WS_STRIDE + k]);
                b[1] = __float_as_uint(bBase[g * 32 * WS_STRIDE + k + 4]);
                mma_tf32(acc[g], a, b);
            }
        }

        #pragma unroll
        for (int rr = 0; rr < 2; rr++) {
            int b = bb0 + r0l + rr * 8;
            float2 xr, xz, xn;
            if (!layer) { xr = x0r; xz = x0z; xn = x0n; }
            else {
                const float* gxp = g_gx1 + ((size_t)b * NT + t) * NG;
                xr = *(const float2*)(gxp + jg);
                xz = *(const float2*)(gxp + NH + jg);
                xn = *(const float2*)(gxp + 2 * NH + jg);
            }
            float2 hp = __ldcg((const float2*)(hc + (size_t)b * NH + jg));

            float r_0 = sigmoidf_(xr.x + acc[0][rr * 2 + 0] + br2.x);
            float r_1 = sigmoidf_(xr.y + acc[0][rr * 2 + 1] + br2.y);
            float u_0 = sigmoidf_(xz.x + acc[1][rr * 2 + 0] + bz2.x);
            float u_1 = sigmoidf_(xz.y + acc[1][rr * 2 + 1] + bz2.y);
            float n_0 = tanhf(xn.x + r_0 * (acc[2][rr * 2 + 0] + bn2.x));
            float n_1 = tanhf(xn.y + r_1 * (acc[2][rr * 2 + 1] + bn2.y));
            float2 hv;
            hv.x = (1.f - u_0) * n_0 + u_0 * hp.x;
            hv.y = (1.f - u_1) * n_1 + u_1 * hp.y;
            __stcg((float2*)(hn_out + (size_t)b * NH + jg), hv);
            float* yrow = ybase + ((size_t)b * NT + t) * NH;
            if (!layer) {
                yrow[pj0] = f2tf32(hv.x);      // K-permuted tf32 for GEMM A
                yrow[pj1] = f2tf32(hv.y);
            } else {
                *(float2*)(yrow + jg) = hv;    // plain (consumed by LN)
            }
        }

        // ---- sub-barrier: only the 8 blocks sharing this batch tile ----
        __threadfence();
        __syncthreads();
        if (tid == 0) {
            atomicAdd(&g_cnt2[layer][t][blockIdx.x], 1u);
            volatile unsigned* p = &g_cnt2[layer][t][blockIdx.x];
            while (*p < 8u) { }
        }
        __syncthreads();
    }
}

// ---------------- LayerNorm + ELU (tf32-rounded, K-permuted store) -----------
__global__ void ln_elu_kernel(const float* __restrict__ gam,
                              const float* __restrict__ bet) {
    int row = blockIdx.x;
    int tid = threadIdx.x;
    float v = g_y1[(size_t)row * NH + tid];

    __shared__ float red[8];
    float s = v;
    #pragma unroll
    for (int o = 16; o; o >>= 1) s += __shfl_xor_sync(0xffffffffu, s, o);
    if ((tid & 31) == 0) red[tid >> 5] = s;
    __syncthreads();
    float tot = red[0] + red[1] + red[2] + red[3] + red[4] + red[5] + red[6] + red[7];
    float mu = tot * (1.f / NH);
    __syncthreads();

    float d = v - mu;
    s = d * d;
    #pragma unroll
    for (int o = 16; o; o >>= 1) s += __shfl_xor_sync(0xffffffffu, s, o);
    if ((tid & 31) == 0) red[tid >> 5] = s;
    __syncthreads();
    tot = red[0] + red[1] + red[2] + red[3] + red[4] + red[5] + red[6] + red[7];
    float var = tot * (1.f / NH);

    float yv = d * rsqrtf(var + 1e-5f) * gam[tid] + bet[tid];
    yv = yv > 0.f ? yv : (__expf(yv) - 1.f);
    g_act[(size_t)row * NH + kperm(tid)] = f2tf32(yv);
}

// ---------------- pipelined tf32 GEMM (swizzled, vectorized fragments) -------
// A: M x 256 (tf32, K-permuted), B: Npad x 256 (tf32, K-permuted).
// smem row = 32 floats = 8 float4-chunks; phys chunk = chunk ^ ((row&1)<<2).
__global__ __launch_bounds__(256, 2) void gemm_pipe_kernel(
    const float* __restrict__ A, const float* __restrict__ Bm,
    const float* __restrict__ bias, float* __restrict__ C, int Nstore) {
    const int K = NH;
    extern __shared__ float sm[];
    float* sA[2] = { sm,             sm + 8192 };
    float* sB[2] = { sm + 4096,      sm + 12288 };

    const int tid = threadIdx.x;
    const int lane = tid & 31;
    const int warp = tid >> 5;
    const int wm = warp & 1;
    const int wn = warp >> 1;
    const int m0 = blockIdx.y * 128;
    const int n0 = blockIdx.x * 128;

    // staging coords: row = tid>>3 (+32*i), chunk = tid&7
    const int srow = tid >> 3;
    const int sck = tid & 7;

    float acc[4][4][4];
    #pragma unroll
    for (int a = 0; a < 4; a++)
        #pragma unroll
        for (int b = 0; b < 4; b++)
            #pragma unroll
            for (int c = 0; c < 4; c++) acc[a][b][c] = 0.f;

    // prologue: stage K-tile 0
    #pragma unroll
    for (int i = 0; i < 4; i++) {
        int r = srow + i * 32;
        int pc = sck ^ ((r & 1) << 2);
        cp_async16(sA[0] + r * 32 + pc * 4, A + (size_t)(m0 + r) * K + sck * 4);
        cp_async16(sB[0] + r * 32 + pc * 4, Bm + (size_t)(n0 + r) * K + sck * 4);
    }
    asm volatile("cp.async.commit_group;");

    const int ra = wm * 64 + (lane >> 2);
    const int rb = wn * 32 + (lane >> 2);
    const int c = lane & 3;

    #pragma unroll
    for (int kt = 0; kt < 8; kt++) {
        const int buf = kt & 1;
        asm volatile("cp.async.wait_group 0;");
        __syncthreads();
        if (kt + 1 < 8) {
            const int nb = buf ^ 1;
            const int ko = (kt + 1) * 32;
            #pragma unroll
            for (int i = 0; i < 4; i++) {
                int r = srow + i * 32;
                int pc = sck ^ ((r & 1) << 2);
                cp_async16(sA[nb] + r * 32 + pc * 4, A + (size_t)(m0 + r) * K + ko + sck * 4);
                cp_async16(sB[nb] + r * 32 + pc * 4, Bm + (size_t)(n0 + r) * K + ko + sck * 4);
            }
            asm volatile("cp.async.commit_group;");
        }

        const float* sAb = sA[buf];
        const float* sBb = sB[buf];
        #pragma unroll
        for (int b16 = 0; b16 < 2; b16++) {
            float4 bf[4];
            #pragma unroll
            for (int nf = 0; nf < 4; nf++) {
                int rr = rb + nf * 8;
                int pc = (b16 * 4 + c) ^ ((rr & 1) << 2);
                bf[nf] = *(const float4*)(sBb + rr * 32 + pc * 4);
            }
            #pragma unroll
            for (int mf = 0; mf < 4; mf++) {
                int r0 = ra + mf * 16;
                int pc = (b16 * 4 + c) ^ ((r0 & 1) << 2);   // r0 and r0+8 same parity
                float4 a0 = *(const float4*)(sAb + r0 * 32 + pc * 4);
                float4 a1 = *(const float4*)(sAb + (r0 + 8) * 32 + pc * 4);
                uint32_t afA[4] = { __float_as_uint(a0.x), __float_as_uint(a1.x),
                                   __float_as_uint(a0.y), __float_as_uint(a1.y) };
                uint32_t afB[4] = { __float_as_uint(a0.z), __float_as_uint(a1.z),
                                   __float_as_uint(a0.w), __float_as_uint(a1.w) };
                #pragma unroll
                for (int nf = 0; nf < 4; nf++) {
                    uint32_t b0[2] = { __float_as_uint(bf[nf].x), __float_as_uint(bf[nf].y) };
                    uint32_t b1[2] = { __float_as_uint(bf[nf].z), __float_as_uint(bf[nf].w) };
                    mma_tf32(acc[mf][nf], afA, b0);
                    mma_tf32(acc[mf][nf], afB, b1);
                }
            }
        }
        __syncthreads();
    }

    // epilogue: add bias, store (guard col < Nstore)
    #pragma unroll
    for (int mf = 0; mf < 4; mf++) {
        int row = m0 + wm * 64 + mf * 16 + (lane >> 2);
        #pragma unroll
        for (int nf = 0; nf < 4; nf++) {
            int col = n0 + wn * 32 + nf * 8 + (lane & 3) * 2;
            if (col < Nstore) {
                float2 bv = *(const float2*)(bias + col);
                float2 o0 = make_float2(acc[mf][nf][0] + bv.x, acc[mf][nf][1] + bv.y);
                float2 o1 = make_float2(acc[mf][nf][2] + bv.x, acc[mf][nf][3] + bv.y);
                *(float2*)(C + (size_t)row * Nstore + col) = o0;
                *(float2*)(C + (size_t)(row + 8) * Nstore + col) = o1;
            }
        }
    }
}

// ---------------- launch -----------------------------------------------------
extern "C" void kernel_launch(void* const* d_in, const int* in_sizes, int n_in,
                              void* d_out, int out_size) {
    const float* z      = (const float*)d_in[0];
    const float* W_init = (const float*)d_in[1];
    const float* b_init = (const float*)d_in[2];
    const float* emb    = (const float*)d_in[3];
    const float* W_ih0  = (const float*)d_in[4];
    const float* W_hh0  = (const float*)d_in[5];
    const float* b_ih0  = (const float*)d_in[6];
    const float* b_hh0  = (const float*)d_in[7];
    const float* W_ih1  = (const float*)d_in[8];
    const float* W_hh1  = (const float*)d_in[9];
    const float* b_ih1  = (const float*)d_in[10];
    const float* b_hh1  = (const float*)d_in[11];
    const float* ln_g   = (const float*)d_in[12];
    const float* ln_b   = (const float*)d_in[13];
    const float* W_out  = (const float*)d_in[14];
    const float* b_out  = (const float*)d_in[15];
    float* out = (float*)d_out;

    static bool attr_done = false;
    if (!attr_done) {
        cudaFuncSetAttribute(gru_persist_kernel,
                             cudaFuncAttributeMaxDynamicSharedMemorySize, GRU_SMEM);
        cudaFuncSetAttribute(gemm_pipe_kernel,
                             cudaFuncAttributeMaxDynamicSharedMemorySize, GEMM_SMEM);
        attr_done = true;
    }

    float* Wih1c; cudaGetSymbolAddress((void**)&Wih1c, g_Wih1c);
    float* Woutc; cudaGetSymbolAddress((void**)&Woutc, g_Woutc);
    float* y0;    cudaGetSymbolAddress((void**)&y0, g_y0);
    float* act;   cudaGetSymbolAddress((void**)&act, g_act);
    float* gx1;   cudaGetSymbolAddress((void**)&gx1, g_gx1);

    reset_kernel<<<8, 256>>>();
    prep1_kernel<<<NB + 3, 256>>>(z, W_init, b_init, emb, W_ih0, b_ih0);
    convw_kernel<<<2720, 256>>>(W_ih1, W_out);

    // GRU layer 0 (persistent)
    gru_persist_kernel<<<dim3(16, 8), 256, GRU_SMEM>>>(0, W_hh0, b_hh0);

    // gx1 = Y0 @ W_ih1^T + b_ih1
    gemm_pipe_kernel<<<dim3(NG / 128, MTOT / 128), 256, GEMM_SMEM>>>(
        y0, Wih1c, b_ih1, gx1, NG);

    // GRU layer 1 (persistent)
    gru_persist_kernel<<<dim3(16, 8), 256, GRU_SMEM>>>(1, W_hh1, b_hh1);

    // LayerNorm + ELU
    ln_elu_kernel<<<MTOT, 256>>>(ln_g, ln_b);

    // logits = act @ W_out^T + b_out
    gemm_pipe_kernel<<<dim3(NPAD / 128, MTOT / 128), 256, GEMM_SMEM>>>(
        act, Woutc, b_out, out, NP);
}

// round 10
// speedup vs baseline: 3.4618x; 1.0457x over previous
#include <cuda_runtime.h>
#include <cstdint>
#include <math.h>

// Problem dims
#define NB 512
#define NZ 64
#define NH 256
#define NG 768   // 3*H
#define NT 64
#define NP 10000
#define NPAD 10112          // NP padded to 128
#define MTOT (NB * NT)      // 32768

#define AS_STRIDE 268
#define WS_STRIDE 260
#define GRU_SMEM ((32 * AS_STRIDE + 96 * WS_STRIDE) * 4)

// GEMM: swizzled 32-float rows, 3 cp.async stages
#define GEMM_SMEM (3 * 2 * 128 * 32 * 4)   // 96 KB

// ---------------- scratch (device globals; no allocations allowed) ----------
__device__ float g_h0[NB * NH];
__device__ float g_g0[NG];
__device__ float g_st0[2][NB * NH];
__device__ float g_st1[2][NB * NH];
__device__ float g_y0[MTOT * NH];            // layer0 outputs, tf32, K-permuted
__device__ float g_gx1[(size_t)MTOT * NG];
__device__ float g_y1[MTOT * NH];            // layer1 outputs (fp32, pre-LN)
__device__ float g_act[MTOT * NH];           // post LN+ELU, tf32, K-permuted
__device__ float g_Wih1c[NG * NH];           // tf32, K-permuted
__device__ float g_Woutc[NPAD * NH];         // tf32, K-permuted, zero padded
__device__ unsigned g_cnt2[2][NT][16];       // per-(layer,t,batch-tile) barrier

// ---------------- helpers ----------------------------------------------------
__device__ __forceinline__ float f2tf32(float f) {
    uint32_t u;
    asm("cvt.rna.tf32.f32 %0, %1;" : "=r"(u) : "f"(f));
    return __uint_as_float(u);
}

__device__ __forceinline__ int kperm(int k) {
    return (k & ~15) | ((k & 3) << 2) | ((k >> 2) & 3);
}

__device__ __forceinline__ void mma_tf32(float* c, const uint32_t* a, const uint32_t* b) {
    asm volatile(
        "mma.sync.aligned.m16n8k8.row.col.f32.tf32.tf32.f32 "
        "{%0,%1,%2,%3},{%4,%5,%6,%7},{%8,%9},{%0,%1,%2,%3};"
        : "+f"(c[0]), "+f"(c[1]), "+f"(c[2]), "+f"(c[3])
        : "r"(a[0]), "r"(a[1]), "r"(a[2]), "r"(a[3]), "r"(b[0]), "r"(b[1]));
}

__device__ __forceinline__ float sigmoidf_(float x) {
    return 1.f / (1.f + __expf(-x));
}

__device__ __forceinline__ void cp_async16(void* smem_dst, const void* gsrc) {
    unsigned a = (unsigned)__cvta_generic_to_shared(smem_dst);
    asm volatile("cp.async.cg.shared.global [%0], [%1], 16;" :: "r"(a), "l"(gsrc));
}

// ---------------- reset barrier counters -------------------------------------
__global__ void reset_kernel() {
    int i = blockIdx.x * blockDim.x + threadIdx.x;   // 2*64*16 = 2048
    ((unsigned*)g_cnt2)[i] = 0u;
}

// ---------------- prep 1: h0 = ELU(z @ W_init^T + b_init); g0 ---------------
__global__ void prep1_kernel(const float* __restrict__ z,
                             const float* __restrict__ Wi,
                             const float* __restrict__ bi,
                             const float* __restrict__ emb,
                             const float* __restrict__ Wih0,
                             const float* __restrict__ bih0) {
    int blk = blockIdx.x;
    int tid = threadIdx.x;   // 256
    if (blk < NB) {
        __shared__ float zs[NZ];
        if (tid < NZ) zs[tid] = z[blk * NZ + tid];
        __syncthreads();
        float acc = bi[tid];
        #pragma unroll 8
        for (int k = 0; k < NZ; k++) acc = fmaf(zs[k], Wi[tid * NZ + k], acc);
        float h = acc > 0.f ? acc : (expf(acc) - 1.f);
        g_h0[blk * NH + tid] = h;
        g_st0[0][blk * NH + tid] = h;
        g_st1[0][blk * NH + tid] = h;
    } else {
        __shared__ float es[NH];
        es[tid] = emb[tid];
        __syncthreads();
        int g = (blk - NB) * NH + tid;
        float acc = bih0[g];
        #pragma unroll 8
        for (int k = 0; k < NH; k++) acc = fmaf(es[k], Wih0[g * NH + k], acc);
        g_g0[g] = acc;
    }
}

// ---------------- prep: tf32 + K-permuted copies of B matrices ---------------
__global__ void convw_kernel(const float* __restrict__ Wih1,
                             const float* __restrict__ Wout) {
    int idx = blockIdx.x * blockDim.x + threadIdx.x;
    const int n1 = NG * NH;
    const int n2 = NPAD * NH;
    if (idx < n1) {
        int row = idx >> 8, col = idx & 255;
        g_Wih1c[(row << 8) | kperm(col)] = f2tf32(Wih1[idx]);
    }
    for (int j = idx; j < n2; j += gridDim.x * blockDim.x) {
        int row = j >> 8, col = j & 255;
        g_Woutc[(row << 8) | kperm(col)] = (row < NP) ? f2tf32(Wout[j]) : 0.f;
    }
}

// ---------------- persistent GRU layer kernel --------------------------------
__global__ __launch_bounds__(256, 1) void gru_persist_kernel(
    int layer, const float* __restrict__ Whh, const float* __restrict__ bhh) {
    extern __shared__ float smem[];
    float* As = smem;
    float* Ws = smem + 32 * AS_STRIDE;

    const int tid = threadIdx.x;
    const int lane = tid & 31;
    const int warp = tid >> 5;
    const int wm = warp & 1;
    const int wn = warp >> 1;
    const int bb0 = blockIdx.x * 32;
    const int hj0 = blockIdx.y * 32;

    float* st[2];
    if (layer) { st[0] = g_st1[0]; st[1] = g_st1[1]; }
    else       { st[0] = g_st0[0]; st[1] = g_st0[1]; }
    float* ybase = layer ? g_y1 : g_y0;

    #pragma unroll
    for (int i = 0; i < 24; i++) {
        int f = tid + i * 256;
        int rr = f >> 6;
        int c4 = (f & 63) << 2;
        int gate = rr >> 5;
        int r = rr & 31;
        float4 v = *(const float4*)(Whh + (size_t)(gate * NH + hj0 + r) * NH + c4);
        float4 w;
        w.x = f2tf32(v.x); w.y = f2tf32(v.y); w.z = f2tf32(v.z); w.w = f2tf32(v.w);
        *(float4*)(Ws + rr * WS_STRIDE + c4) = w;
    }

    const int r0l = wm * 16 + (lane >> 2);
    const int cl = wn * 8 + (lane & 3) * 2;
    const int jg = hj0 + cl;
    const int pj0 = kperm(jg);
    const int pj1 = kperm(jg + 1);

    const float2 br2 = *(const float2*)(bhh + jg);
    const float2 bz2 = *(const float2*)(bhh + NH + jg);
    const float2 bn2 = *(const float2*)(bhh + 2 * NH + jg);
    float2 x0r, x0z, x0n;
    if (!layer) {
        x0r = *(const float2*)(g_g0 + jg);
        x0z = *(const float2*)(g_g0 + NH + jg);
        x0n = *(const float2*)(g_g0 + 2 * NH + jg);
    }

    const float* aBase = As + (size_t)r0l * AS_STRIDE + (lane & 3);
    const float* bBase = Ws + (size_t)(wn * 8 + (lane >> 2)) * WS_STRIDE + (lane & 3);

    __syncthreads();

    for (int t = 0; t < NT; t++) {
        const float* hc = st[t & 1];
        float* hn_out = st[(t + 1) & 1];

        // ---- prefetch x-gates and h_prev for the update (independent of
        //      the h-tile staging; hides L2 latency behind the MMA chain) ----
        float2 xr[2], xz[2], xn[2], hp[2];
        #pragma unroll
        for (int rr = 0; rr < 2; rr++) {
            int b = bb0 + r0l + rr * 8;
            if (!layer) { xr[rr] = x0r; xz[rr] = x0z; xn[rr] = x0n; }
            else {
                const float* gxp = g_gx1 + ((size_t)b * NT + t) * NG;
                xr[rr] = *(const float2*)(gxp + jg);
                xz[rr] = *(const float2*)(gxp + NH + jg);
                xn[rr] = *(const float2*)(gxp + 2 * NH + jg);
            }
            hp[rr] = __ldcg((const float2*)(hc + (size_t)b * NH + jg));
        }

        // ---- stage h tile (L2-coherent loads), convert to tf32 ----
        #pragma unroll
        for (int i = 0; i < 8; i++) {
            int f = tid + i * 256;
            int row = f >> 6;
            int c4 = (f & 63) << 2;
            float4 v = __ldcg((const float4*)(hc + (size_t)(bb0 + row) * NH + c4));
            float4 w;
            w.x = f2tf32(v.x); w.y = f2tf32(v.y); w.z = f2tf32(v.z); w.w = f2tf32(v.w);
            *(float4*)(As + row * AS_STRIDE + c4) = w;
        }
        __syncthreads();

        float acc[3][4];
        #pragma unroll
        for (int g = 0; g < 3; g++)
            #pragma unroll
            for (int c = 0; c < 4; c++) acc[g][c] = 0.f;

        #pragma unroll 8
        for (int k = 0; k < NH; k += 8) {
            uint32_t a[4], b[2];
            a[0] = __float_as_uint(aBase[k]);
            a[1] = __float_as_uint(aBase[8 * AS_STRIDE + k]);
            a[2] = __float_as_uint(aBase[k + 4]);
            a[3] = __float_as_uint(aBase[8 * AS_STRIDE + k + 4]);
            #pragma unroll
            for (int g = 0; g < 3; g++) {
                b[0] = __float_as_uint(bBase[g * 32 * WS_STRIDE + k]);
                b[1] = __float_as_uint(bBase[g * 32 * WS_STRIDE + k + 4]);
                mma_tf32(acc[g], a, b);
            }
        }

        #pragma unroll
        for (int rr = 0; rr < 2; rr++) {
            int b = bb0 + r0l + rr * 8;
            float r_0 = sigmoidf_(xr[rr].x + acc[0][rr * 2 + 0] + br2.x);
            float r_1 = sigmoidf_(xr[rr].y + acc[0][rr * 2 + 1] + br2.y);
            float u_0 = sigmoidf_(xz[rr].x + acc[1][rr * 2 + 0] + bz2.x);
            float u_1 = sigmoidf_(xz[rr].y + acc[1][rr * 2 + 1] + bz2.y);
            float n_0 = tanhf(xn[rr].x + r_0 * (acc[2][rr * 2 + 0] + bn2.x));
            float n_1 = tanhf(xn[rr].y + r_1 * (acc[2][rr * 2 + 1] + bn2.y));
            float2 hv;
            hv.x = (1.f - u_0) * n_0 + u_0 * hp[rr].x;
            hv.y = (1.f - u_1) * n_1 + u_1 * hp[rr].y;
            __stcg((float2*)(hn_out + (size_t)b * NH + jg), hv);
            float* yrow = ybase + ((size_t)b * NT + t) * NH;
            if (!layer) {
                yrow[pj0] = f2tf32(hv.x);      // K-permuted tf32 for gx1 GEMM
                yrow[pj1] = f2tf32(hv.y);
            } else {
                *(float2*)(yrow + jg) = hv;    // plain (consumed by LN)
            }
        }

        // ---- sub-barrier: only the 8 blocks sharing this batch tile ----
        __threadfence();
        __syncthreads();
        if (tid == 0) {
            atomicAdd(&g_cnt2[layer][t][blockIdx.x], 1u);
            volatile unsigned* p = &g_cnt2[layer][t][blockIdx.x];
            while (*p < 8u) { }
        }
        __syncthreads();
    }
}

// ---------------- LayerNorm + ELU (tf32-rounded, K-permuted store) -----------
__global__ void ln_elu_kernel(const float* __restrict__ gam,
                              const float* __restrict__ bet) {
    int row = blockIdx.x;
    int tid = threadIdx.x;
    float v = g_y1[(size_t)row * NH + tid];

    __shared__ float red[8];
    float s = v;
    #pragma unroll
    for (int o = 16; o; o >>= 1) s += __shfl_xor_sync(0xffffffffu, s, o);
    if ((tid & 31) == 0) red[tid >> 5] = s;
    __syncthreads();
    float tot = red[0] + red[1] + red[2] + red[3] + red[4] + red[5] + red[6] + red[7];
    float mu = tot * (1.f / NH);
    __syncthreads();

    float d = v - mu;
    s = d * d;
    #pragma unroll
    for (int o = 16; o; o >>= 1) s += __shfl_xor_sync(0xffffffffu, s, o);
    if ((tid & 31) == 0) red[tid >> 5] = s;
    __syncthreads();
    tot = red[0] + red[1] + red[2] + red[3] + red[4] + red[5] + red[6] + red[7];
    float var = tot * (1.f / NH);

    float yv = d * rsqrtf(var + 1e-5f) * gam[tid] + bet[tid];
    yv = yv > 0.f ? yv : (__expf(yv) - 1.f);
    g_act[(size_t)row * NH + kperm(tid)] = f2tf32(yv);
}

// ---------------- 3-stage pipelined tf32 GEMM (one sync per K-tile) ----------
// A: M x 256 (tf32, K-permuted), B: Npad x 256 (tf32, K-permuted).
// smem row = 32 floats = 8 float4-chunks; phys chunk = chunk ^ ((row&1)<<2).
// Stage s occupies sm + s*8192 (A: 4096 floats, B: 4096 floats).
__global__ __launch_bounds__(256, 2) void gemm_pipe_kernel(
    const float* __restrict__ A, const float* __restrict__ Bm,
    const float* __restrict__ bias, float* __restrict__ C, int Nstore) {
    const int K = NH;
    extern __shared__ float sm[];

    const int tid = threadIdx.x;
    const int lane = tid & 31;
    const int warp = tid >> 5;
    const int wm = warp & 1;
    const int wn = warp >> 1;
    const int m0 = blockIdx.y * 128;
    const int n0 = blockIdx.x * 128;

    const int srow = tid >> 3;          // 0..31 (+32*i)
    const int sck = tid & 7;

    float acc[4][4][4];
    #pragma unroll
    for (int a = 0; a < 4; a++)
        #pragma unroll
        for (int b = 0; b < 4; b++)
            #pragma unroll
            for (int c = 0; c < 4; c++) acc[a][b][c] = 0.f;

    auto stagef = [&](int kt, int s) {
        const int ko = kt * 32;
        float* dA = sm + s * 8192;
        float* dB = dA + 4096;
        #pragma unroll
        for (int i = 0; i < 4; i++) {
            int r = srow + i * 32;
            int pc = sck ^ ((r & 1) << 2);
            cp_async16(dA + r * 32 + pc * 4, A + (size_t)(m0 + r) * K + ko + sck * 4);
            cp_async16(dB + r * 32 + pc * 4, Bm + (size_t)(n0 + r) * K + ko + sck * 4);
        }
        asm volatile("cp.async.commit_group;");
    };

    // prologue: two tiles in flight
    stagef(0, 0);
    stagef(1, 1);

    const int ra = wm * 64 + (lane >> 2);
    const int rb = wn * 32 + (lane >> 2);
    const int c = lane & 3;

    #pragma unroll
    for (int kt = 0; kt < 8; kt++) {
        if (kt < 7) asm volatile("cp.async.wait_group 1;");
        else        asm volatile("cp.async.wait_group 0;");
        __syncthreads();
        // stage kt+2 into buffer (kt+2)%3 == (kt-1)%3: its previous readers
        // (compute of tile kt-1) are all past the sync above.
        if (kt + 2 < 8) stagef(kt + 2, (kt + 2) % 3);

        const float* sAb = sm + (kt % 3) * 8192;
        const float* sBb = sAb + 4096;
        #pragma unroll
        for (int b16 = 0; b16 < 2; b16++) {
            float4 bf[4];
            #pragma unroll
            for (int nf = 0; nf < 4; nf++) {
                int rr = rb + nf * 8;
                int pc = (b16 * 4 + c) ^ ((rr & 1) << 2);
                bf[nf] = *(const float4*)(sBb + rr * 32 + pc * 4);
            }
            #pragma unroll
            for (int mf = 0; mf < 4; mf++) {
                int r0 = ra + mf * 16;
                int pc = (b16 * 4 + c) ^ ((r0 & 1) << 2);
                float4 a0 = *(const float4*)(sAb + r0 * 32 + pc * 4);
                float4 a1 = *(const float4*)(sAb + (r0 + 8) * 32 + pc * 4);
                uint32_t afA[4] = { __float_as_uint(a0.x), __float_as_uint(a1.x),
                                   __float_as_uint(a0.y), __float_as_uint(a1.y) };
                uint32_t afB[4] = { __float_as_uint(a0.z), __float_as_uint(a1.z),
                                   __float_as_uint(a0.w), __float_as_uint(a1.w) };
                #pragma unroll
                for (int nf = 0; nf < 4; nf++) {
                    uint32_t b0[2] = { __float_as_uint(bf[nf].x), __float_as_uint(bf[nf].y) };
                    uint32_t b1[2] = { __float_as_uint(bf[nf].z), __float_as_uint(bf[nf].w) };
                    mma_tf32(acc[mf][nf], afA, b0);
                    mma_tf32(acc[mf][nf], afB, b1);
                }
            }
        }
    }

    // epilogue: add bias, store (guard col < Nstore)
    __syncthreads();
    #pragma unroll
    for (int mf = 0; mf < 4; mf++) {
        int row = m0 + wm * 64 + mf * 16 + (lane >> 2);
        #pragma unroll
        for (int nf = 0; nf < 4; nf++) {
            int col = n0 + wn * 32 + nf * 8 + (lane & 3) * 2;
            if (col < Nstore) {
                float2 bv = *(const float2*)(bias + col);
                float2 o0 = make_float2(acc[mf][nf][0] + bv.x, acc[mf][nf][1] + bv.y);
                float2 o1 = make_float2(acc[mf][nf][2] + bv.x, acc[mf][nf][3] + bv.y);
                *(float2*)(C + (size_t)row * Nstore + col) = o0;
                *(float2*)(C + (size_t)(row + 8) * Nstore + col) = o1;
            }
        }
    }
}

// ---------------- launch -----------------------------------------------------
extern "C" void kernel_launch(void* const* d_in, const int* in_sizes, int n_in,
                              void* d_out, int out_size) {
    const float* z      = (const float*)d_in[0];
    const float* W_init = (const float*)d_in[1];
    const float* b_init = (const float*)d_in[2];
    const float* emb    = (const float*)d_in[3];
    const float* W_ih0  = (const float*)d_in[4];
    const float* W_hh0  = (const float*)d_in[5];
    const float* b_ih0  = (const float*)d_in[6];
    const float* b_hh0  = (const float*)d_in[7];
    const float* W_ih1  = (const float*)d_in[8];
    const float* W_hh1  = (const float*)d_in[9];
    const float* b_ih1  = (const float*)d_in[10];
    const float* b_hh1  = (const float*)d_in[11];
    const float* ln_g   = (const float*)d_in[12];
    const float* ln_b   = (const float*)d_in[13];
    const float* W_out  = (const float*)d_in[14];
    const float* b_out  = (const float*)d_in[15];
    float* out = (float*)d_out;

    static bool attr_done = false;
    if (!attr_done) {
        cudaFuncSetAttribute(gru_persist_kernel,
                             cudaFuncAttributeMaxDynamicSharedMemorySize, GRU_SMEM);
        cudaFuncSetAttribute(gemm_pipe_kernel,
                             cudaFuncAttributeMaxDynamicSharedMemorySize, GEMM_SMEM);
        attr_done = true;
    }

    float* Wih1c; cudaGetSymbolAddress((void**)&Wih1c, g_Wih1c);
    float* Woutc; cudaGetSymbolAddress((void**)&Woutc, g_Woutc);
    float* y0;    cudaGetSymbolAddress((void**)&y0, g_y0);
    float* act;   cudaGetSymbolAddress((void**)&act, g_act);
    float* gx1;   cudaGetSymbolAddress((void**)&gx1, g_gx1);

    reset_kernel<<<8, 256>>>();
    prep1_kernel<<<NB + 3, 256>>>(z, W_init, b_init, emb, W_ih0, b_ih0);
    convw_kernel<<<2720, 256>>>(W_ih1, W_out);

    // GRU layer 0 (persistent)
    gru_persist_kernel<<<dim3(16, 8), 256, GRU_SMEM>>>(0, W_hh0, b_hh0);

    // gx1 = Y0 @ W_ih1^T + b_ih1
    gemm_pipe_kernel<<<dim3(NG / 128, MTOT / 128), 256, GEMM_SMEM>>>(
        y0, Wih1c, b_ih1, gx1, NG);

    // GRU layer 1 (persistent)
    gru_persist_kernel<<<dim3(16, 8), 256, GRU_SMEM>>>(1, W_hh1, b_hh1);

    // LayerNorm + ELU
    ln_elu_kernel<<<MTOT, 256>>>(ln_g, ln_b);

    // logits = act @ W_out^T + b_out
    gemm_pipe_kernel<<<dim3(NPAD / 128, MTOT / 128), 256, GEMM_SMEM>>>(
        act, Woutc, b_out, out, NP);
}